// round 1
// baseline (speedup 1.0000x reference)
#include <cuda_runtime.h>
#include <math.h>

#define Bsz  2
#define T    1024
#define C    1024
#define NH   16
#define DH   64
#define L    4
#define HFF  2816
#define FEAT 9
#define M    (Bsz * T)   // 2048

// ---------------- scratch (static device globals; no allocation at runtime) ----
__device__ float g_h  [M * C];
__device__ float g_nrm[M * C];
__device__ float g_q  [M * C];
__device__ float g_kv [M * 2 * C];
__device__ float g_y  [M * C];
__device__ float g_h1 [M * HFF];
__device__ float g_h2 [M * HFF];
__device__ float g_cos[T * DH];
__device__ float g_sin[T * DH];

// ---------------- RoPE tables ------------------------------------------------
__global__ void rope_init_kernel() {
    int idx = blockIdx.x * 256 + threadIdx.x;   // T*32 = 32768 threads
    int t = idx >> 5, j = idx & 31;
    float inv = powf(10000.0f, -((float)(2 * j) / (float)DH));
    float ang = (float)t * inv;
    float c = cosf(ang), s = sinf(ang);
    g_cos[t * DH + j]      = c;
    g_cos[t * DH + j + 32] = c;
    g_sin[t * DH + j]      = s;
    g_sin[t * DH + j + 32] = s;
}

// ---------------- input projection: h = x @ w_in^T  (K = 9) ------------------
__global__ __launch_bounds__(256) void inproj_kernel(const float* __restrict__ x,
                                                     const float* __restrict__ w,
                                                     float* __restrict__ h) {
    __shared__ float xs[FEAT];
    int m = blockIdx.x;
    if (threadIdx.x < FEAT) xs[threadIdx.x] = x[(size_t)m * FEAT + threadIdx.x];
    __syncthreads();
    for (int c = threadIdx.x; c < C; c += 256) {
        float s = 0.f;
#pragma unroll
        for (int f = 0; f < FEAT; f++) s += xs[f] * w[c * FEAT + f];
        h[(size_t)m * C + c] = s;
    }
}

// ---------------- RMSNorm: out = in * rsqrt(mean(in^2)+eps) * g ---------------
__global__ __launch_bounds__(256) void rms_kernel(const float* __restrict__ in,
                                                  const float* __restrict__ g,
                                                  float* __restrict__ out, int nc) {
    int m = blockIdx.x;
    int tid = threadIdx.x;
    const float* row = in + (size_t)m * nc;
    float ss = 0.f;
    for (int c = tid; c < nc; c += 256) { float v = row[c]; ss += v * v; }
#pragma unroll
    for (int o = 16; o > 0; o >>= 1) ss += __shfl_xor_sync(0xffffffffu, ss, o);
    __shared__ float red[8];
    if ((tid & 31) == 0) red[tid >> 5] = ss;
    __syncthreads();
    if (tid < 8) {
        float v = red[tid];
#pragma unroll
        for (int o = 4; o > 0; o >>= 1) v += __shfl_xor_sync(0xffu, v, o);
        if (tid == 0) red[0] = v;
    }
    __syncthreads();
    float r = rsqrtf(red[0] / (float)nc + 1e-5f);
    for (int c = tid; c < nc; c += 256)
        out[(size_t)m * nc + c] = row[c] * r * g[c];
}

// ---------------- SGEMM (NT):  Cmat[M,N] (+)= A[M,K] @ W[N,K]^T ---------------
// 128x128 tile, BK=16, 256 threads, 8x8 microtile.
__global__ __launch_bounds__(256) void sgemm_nt(const float* __restrict__ A,
                                                const float* __restrict__ W,
                                                float* __restrict__ Cmat,
                                                int Mm, int Nn, int Kk, int addTo) {
    __shared__ float As[16][128];
    __shared__ float Bs[16][128];
    const int tid = threadIdx.x;
    const int tx = tid & 15;
    const int ty = tid >> 4;
    const int row0 = blockIdx.y * 128;
    const int col0 = blockIdx.x * 128;

    float acc[8][8];
#pragma unroll
    for (int i = 0; i < 8; i++)
#pragma unroll
        for (int j = 0; j < 8; j++) acc[i][j] = 0.f;

    for (int k0 = 0; k0 < Kk; k0 += 16) {
#pragma unroll
        for (int i = 0; i < 2; i++) {
            int lin = tid + i * 256;            // 0..511 float4 slots
            int r   = lin >> 2;                 // 0..127
            int kc  = (lin & 3) << 2;           // 0,4,8,12
            float4 va = *(const float4*)(A + (size_t)(row0 + r) * Kk + k0 + kc);
            As[kc + 0][r] = va.x; As[kc + 1][r] = va.y;
            As[kc + 2][r] = va.z; As[kc + 3][r] = va.w;
            float4 vb = *(const float4*)(W + (size_t)(col0 + r) * Kk + k0 + kc);
            Bs[kc + 0][r] = vb.x; Bs[kc + 1][r] = vb.y;
            Bs[kc + 2][r] = vb.z; Bs[kc + 3][r] = vb.w;
        }
        __syncthreads();
#pragma unroll
        for (int kk = 0; kk < 16; kk++) {
            float a[8], b[8];
            *(float4*)&a[0] = *(const float4*)&As[kk][ty * 8];
            *(float4*)&a[4] = *(const float4*)&As[kk][ty * 8 + 4];
            *(float4*)&b[0] = *(const float4*)&Bs[kk][tx * 8];
            *(float4*)&b[4] = *(const float4*)&Bs[kk][tx * 8 + 4];
#pragma unroll
            for (int i = 0; i < 8; i++)
#pragma unroll
                for (int j = 0; j < 8; j++) acc[i][j] += a[i] * b[j];
        }
        __syncthreads();
    }
#pragma unroll
    for (int i = 0; i < 8; i++) {
        int r = row0 + ty * 8 + i;
        float* cp = Cmat + (size_t)r * Nn + col0 + tx * 8;
#pragma unroll
        for (int j4 = 0; j4 < 2; j4++) {
            float4 v;
            v.x = acc[i][j4 * 4 + 0]; v.y = acc[i][j4 * 4 + 1];
            v.z = acc[i][j4 * 4 + 2]; v.w = acc[i][j4 * 4 + 3];
            if (addTo) {
                float4 old = *(float4*)(cp + j4 * 4);
                v.x += old.x; v.y += old.y; v.z += old.z; v.w += old.w;
            }
            *(float4*)(cp + j4 * 4) = v;
        }
    }
}

// ---------------- RoPE apply (in place; q stride C, k stride 2C) --------------
__global__ __launch_bounds__(256) void rope_kernel(float* __restrict__ buf, int rowStride) {
    int idx = blockIdx.x * 256 + threadIdx.x;   // M*NH*32 threads
    int j  = idx & 31;
    int hh = (idx >> 5) & (NH - 1);
    int m  = idx >> 9;
    int t  = m & (T - 1);
    float* p = buf + (size_t)m * rowStride + hh * DH;
    float c = g_cos[t * DH + j];
    float s = g_sin[t * DH + j];
    float x0 = p[j], x1 = p[j + 32];
    p[j]      = x0 * c - x1 * s;
    p[j + 32] = x1 * c + x0 * s;
}

// ---------------- flash attention: 1 thread per query, online softmax ---------
__global__ __launch_bounds__(128) void attn_kernel(const float* __restrict__ q,
                                                   const float* __restrict__ kv,
                                                   float* __restrict__ y) {
    __shared__ float Ks[32][DH];
    __shared__ float Vs[32][DH];
    const int tid = threadIdx.x;
    const int b  = blockIdx.y >> 4;
    const int hh = blockIdx.y & 15;
    const int t  = blockIdx.x * 128 + tid;
    const int tEndBlock = blockIdx.x * 128 + 128;

    float qr[DH];
    {
        const float* qp = q + (size_t)(b * T + t) * C + hh * DH;
#pragma unroll
        for (int d = 0; d < DH; d++) qr[d] = qp[d] * 0.125f;  // 1/sqrt(64)
    }
    float orow[DH];
#pragma unroll
    for (int d = 0; d < DH; d++) orow[d] = 0.f;
    float mrun = -1e30f, ssum = 0.f;

    for (int j0 = 0; j0 < tEndBlock; j0 += 32) {
        __syncthreads();
#pragma unroll
        for (int i = 0; i < 4; i++) {
            int lin = tid + i * 128;            // 0..511 float4 slots
            int r   = lin >> 4;                 // 0..31
            int c4  = (lin & 15) << 2;
            size_t base = (size_t)(b * T + j0 + r) * (2 * C) + hh * DH + c4;
            *(float4*)&Ks[r][c4] = *(const float4*)(kv + base);
            *(float4*)&Vs[r][c4] = *(const float4*)(kv + base + C);
        }
        __syncthreads();
        int nj = t - j0 + 1;
        if (nj > 32) nj = 32;
        for (int jj = 0; jj < nj; jj++) {
            float s = 0.f;
#pragma unroll
            for (int d = 0; d < DH; d++) s += qr[d] * Ks[jj][d];
            float mnew = fmaxf(mrun, s);
            float corr = __expf(mrun - mnew);
            float p    = __expf(s - mnew);
            ssum = ssum * corr + p;
#pragma unroll
            for (int d = 0; d < DH; d++)
                orow[d] = orow[d] * corr + p * Vs[jj][d];
            mrun = mnew;
        }
    }
    float inv = 1.f / ssum;
    float* yp = y + (size_t)(b * T + t) * C + hh * DH;
#pragma unroll
    for (int d = 0; d < DH; d++) yp[d] = orow[d] * inv;
}

// ---------------- gated SiLU elementwise: h1 = silu(h1) * h2 ------------------
__global__ void silu_gate_kernel(float* __restrict__ h1, const float* __restrict__ h2, int n) {
    int i = blockIdx.x * blockDim.x + threadIdx.x;
    if (i < n) {
        float a = h1[i];
        float s = a / (1.f + __expf(-a));
        h1[i] = s * h2[i];
    }
}

// ---------------- driver ------------------------------------------------------
extern "C" void kernel_launch(void* const* d_in, const int* in_sizes, int n_in,
                              void* d_out, int out_size) {
    const float* x    = (const float*)d_in[0];
    const float* w_in = (const float*)d_in[1];
    const float* wq   = (const float*)d_in[2];
    const float* wkv  = (const float*)d_in[3];
    const float* wo   = (const float*)d_in[4];
    const float* w1   = (const float*)d_in[5];
    const float* w2   = (const float*)d_in[6];
    const float* w3   = (const float*)d_in[7];
    const float* g1   = (const float*)d_in[8];
    const float* g2   = (const float*)d_in[9];
    const float* gf   = (const float*)d_in[10];

    float *h, *nrm, *qb, *kvb, *yb, *h1, *h2;
    cudaGetSymbolAddress((void**)&h,   g_h);
    cudaGetSymbolAddress((void**)&nrm, g_nrm);
    cudaGetSymbolAddress((void**)&qb,  g_q);
    cudaGetSymbolAddress((void**)&kvb, g_kv);
    cudaGetSymbolAddress((void**)&yb,  g_y);
    cudaGetSymbolAddress((void**)&h1,  g_h1);
    cudaGetSymbolAddress((void**)&h2,  g_h2);

    rope_init_kernel<<<128, 256>>>();
    inproj_kernel<<<M, 256>>>(x, w_in, h);

    for (int l = 0; l < L; l++) {
        // ---- attention block ----
        rms_kernel<<<M, 256>>>(h, g1 + (size_t)l * C, nrm, C);
        sgemm_nt<<<dim3(C / 128, M / 128), 256>>>(nrm, wq  + (size_t)l * C * C,     qb,  M, C,     C,   0);
        sgemm_nt<<<dim3(2 * C / 128, M / 128), 256>>>(nrm, wkv + (size_t)l * 2 * C * C, kvb, M, 2 * C, C, 0);
        rope_kernel<<<4096, 256>>>(qb, C);
        rope_kernel<<<4096, 256>>>(kvb, 2 * C);
        attn_kernel<<<dim3(T / 128, Bsz * NH), 128>>>(qb, kvb, yb);
        sgemm_nt<<<dim3(C / 128, M / 128), 256>>>(yb, wo + (size_t)l * C * C, h, M, C, C, 1);
        // ---- MLP block ----
        rms_kernel<<<M, 256>>>(h, g2 + (size_t)l * C, nrm, C);
        sgemm_nt<<<dim3(HFF / 128, M / 128), 256>>>(nrm, w1 + (size_t)l * HFF * C, h1, M, HFF, C, 0);
        sgemm_nt<<<dim3(HFF / 128, M / 128), 256>>>(nrm, w2 + (size_t)l * HFF * C, h2, M, HFF, C, 0);
        silu_gate_kernel<<<(M * HFF + 255) / 256, 256>>>(h1, h2, M * HFF);
        sgemm_nt<<<dim3(C / 128, M / 128), 256>>>(h1, w3 + (size_t)l * C * HFF, h, M, C, HFF, 1);
    }

    rms_kernel<<<M, 256>>>(h, gf, (float*)d_out, C);
}

// round 3
// speedup vs baseline: 1.5205x; 1.5205x over previous
#include <cuda_runtime.h>
#include <cuda_bf16.h>
#include <math.h>
#include <stdint.h>

#define Bsz  2
#define T    1024
#define C    1024
#define NH   16
#define DH   64
#define L    4
#define HFF  2816
#define FEAT 9
#define M    (Bsz * T)      // 2048
#define KP1  (3 * C)        // 3072
#define KP3  (3 * HFF)      // 8448

// ---------------- scratch (static device globals) -----------------------------
__device__ float g_h  [M * C];
__device__ float g_nrm[M * C];
__device__ float g_q  [M * C];
__device__ float g_kv [M * 2 * C];
__device__ float g_y  [M * C];
__device__ float g_h1 [M * HFF];
__device__ float g_h2 [M * HFF];
__device__ float g_cos[T * DH];
__device__ float g_sin[T * DH];

// bf16 triple-split buffers
__device__ __nv_bfloat16 g_a3  [M * KP3];
__device__ __nv_bfloat16 g_wq3 [L * C   * KP1];
__device__ __nv_bfloat16 g_wkv3[L * 2*C * KP1];
__device__ __nv_bfloat16 g_wo3 [L * C   * KP1];
__device__ __nv_bfloat16 g_w13 [L * HFF * KP1];
__device__ __nv_bfloat16 g_w23 [L * HFF * KP1];
__device__ __nv_bfloat16 g_w33 [L * C   * KP3];

// ---------------- helpers ------------------------------------------------------
__device__ __forceinline__ uint32_t smem_u32(const void* p) {
    uint32_t a;
    asm("{ .reg .u64 t; cvta.to.shared.u64 t, %1; cvt.u32.u64 %0, t; }" : "=r"(a) : "l"(p));
    return a;
}
__device__ __forceinline__ void cp16(uint32_t dst, const void* src) {
    asm volatile("cp.async.cg.shared.global [%0], [%1], 16;" :: "r"(dst), "l"(src));
}
__device__ __forceinline__ void cp_commit() {
    asm volatile("cp.async.commit_group;" ::: "memory");
}
template<int N> __device__ __forceinline__ void cp_wait() {
    asm volatile("cp.async.wait_group %0;" :: "n"(N) : "memory");
}
__device__ __forceinline__ void ldm_x4(uint32_t* r, uint32_t addr) {
    asm volatile("ldmatrix.sync.aligned.m8n8.x4.shared.b16 {%0,%1,%2,%3}, [%4];"
                 : "=r"(r[0]), "=r"(r[1]), "=r"(r[2]), "=r"(r[3]) : "r"(addr));
}
__device__ __forceinline__ void mma16816(float* d, const uint32_t* a, const uint32_t* b) {
    asm volatile("mma.sync.aligned.m16n8k16.row.col.f32.bf16.bf16.f32 "
                 "{%0,%1,%2,%3}, {%4,%5,%6,%7}, {%8,%9}, {%0,%1,%2,%3};"
                 : "+f"(d[0]), "+f"(d[1]), "+f"(d[2]), "+f"(d[3])
                 : "r"(a[0]), "r"(a[1]), "r"(a[2]), "r"(a[3]), "r"(b[0]), "r"(b[1]));
}

// ---------------- pack kernels (hi/lo bf16 split, K-tripled layouts) -----------
// A' = [hi | hi | lo]
__global__ void pack_a3_kernel(const float* __restrict__ A, __nv_bfloat16* __restrict__ out,
                               int K, int n) {
    int i = blockIdx.x * 256 + threadIdx.x;
    if (i >= n) return;
    int m = i / K, k = i - m * K;
    float x = A[i];
    __nv_bfloat16 hi = __float2bfloat16(x);
    __nv_bfloat16 lo = __float2bfloat16(x - __bfloat162float(hi));
    size_t base = (size_t)m * (3 * K) + k;
    out[base] = hi; out[base + K] = hi; out[base + 2 * K] = lo;
}
// B' = [hi | lo | hi]
__global__ void pack_b3_kernel(const float* __restrict__ W, __nv_bfloat16* __restrict__ out,
                               int K, int n) {
    int i = blockIdx.x * 256 + threadIdx.x;
    if (i >= n) return;
    int m = i / K, k = i - m * K;
    float x = W[i];
    __nv_bfloat16 hi = __float2bfloat16(x);
    __nv_bfloat16 lo = __float2bfloat16(x - __bfloat162float(hi));
    size_t base = (size_t)m * (3 * K) + k;
    out[base] = hi; out[base + K] = lo; out[base + 2 * K] = hi;
}

// ---------------- mma.sync bf16 GEMM: Cmat[M,N] (+)= A3[M,Kp] @ B3[N,Kp]^T ----
// 128x128 CTA tile, BK=32, 8 warps (2x4), warp tile 64x32, double-buffered.
#define BM  128
#define BN  128
#define BK  32
#define LDS_ (BK + 8)     // 40 bf16 = 80B row stride (conflict-free for ldmatrix)

__global__ __launch_bounds__(256)
void hgemm(const __nv_bfloat16* __restrict__ A, const __nv_bfloat16* __restrict__ B,
           float* __restrict__ Cmat, int Nn, int Kp, int addTo) {
    __shared__ __nv_bfloat16 As[2][BM][LDS_];
    __shared__ __nv_bfloat16 Bs[2][BN][LDS_];

    const int tid  = threadIdx.x;
    const int lane = tid & 31;
    const int warp = tid >> 5;
    const int wm   = warp & 1;      // 0..1  (m)
    const int wn   = warp >> 1;     // 0..3  (n)
    const int row0 = blockIdx.y * BM;
    const int col0 = blockIdx.x * BN;

    float acc[4][4][4];
#pragma unroll
    for (int i = 0; i < 4; i++)
#pragma unroll
        for (int j = 0; j < 4; j++)
#pragma unroll
            for (int q = 0; q < 4; q++) acc[i][j][q] = 0.f;

    // per-thread copy slots: lin = tid + i*256 -> row = lin>>2, 16B chunk = lin&3
    const int cprow = tid >> 2;
    const int cpc   = (tid & 3) * 8;

    const int nIter = Kp / BK;

    // prologue: stage 0
    {
        const int k0 = 0;
#pragma unroll
        for (int i = 0; i < 2; i++) {
            int r = cprow + i * 64;
            cp16(smem_u32(&As[0][r][cpc]), A + (size_t)(row0 + r) * Kp + k0 + cpc);
            cp16(smem_u32(&Bs[0][r][cpc]), B + (size_t)(col0 + r) * Kp + k0 + cpc);
        }
        cp_commit();
    }

    for (int it = 0; it < nIter; it++) {
        if (it + 1 < nIter) {
            const int k0 = (it + 1) * BK;
            const int s  = (it + 1) & 1;
#pragma unroll
            for (int i = 0; i < 2; i++) {
                int r = cprow + i * 64;
                cp16(smem_u32(&As[s][r][cpc]), A + (size_t)(row0 + r) * Kp + k0 + cpc);
                cp16(smem_u32(&Bs[s][r][cpc]), B + (size_t)(col0 + r) * Kp + k0 + cpc);
            }
            cp_commit();
            cp_wait<1>();
        } else {
            cp_wait<0>();
        }
        __syncthreads();

        const int s = it & 1;
#pragma unroll
        for (int ks = 0; ks < 2; ks++) {
            const int k0 = ks * 16;
            uint32_t af[4][4];
            uint32_t bf[4][2];
            // A fragments: 4 m-tiles of 16 rows
#pragma unroll
            for (int mt = 0; mt < 4; mt++) {
                int r = wm * 64 + mt * 16 + (lane & 15);
                int c = k0 + (lane >> 4) * 8;
                ldm_x4(af[mt], smem_u32(&As[s][r][c]));
            }
            // B fragments: 2 x4 loads cover 4 n-tiles of 8 rows
#pragma unroll
            for (int np = 0; np < 2; np++) {
                uint32_t tmpb[4];
                int r = wn * 32 + np * 16 + ((lane >> 4) << 3) + (lane & 7);
                int c = k0 + ((lane >> 3) & 1) * 8;
                ldm_x4(tmpb, smem_u32(&Bs[s][r][c]));
                bf[np * 2 + 0][0] = tmpb[0]; bf[np * 2 + 0][1] = tmpb[1];
                bf[np * 2 + 1][0] = tmpb[2]; bf[np * 2 + 1][1] = tmpb[3];
            }
#pragma unroll
            for (int mt = 0; mt < 4; mt++)
#pragma unroll
                for (int nt = 0; nt < 4; nt++)
                    mma16816(acc[mt][nt], af[mt], bf[nt]);
        }
        __syncthreads();
    }

    // epilogue
#pragma unroll
    for (int mt = 0; mt < 4; mt++) {
#pragma unroll
        for (int nt = 0; nt < 4; nt++) {
            int r = row0 + wm * 64 + mt * 16 + (lane >> 2);
            int c = col0 + wn * 32 + nt * 8 + (lane & 3) * 2;
            float* p0 = Cmat + (size_t)r * Nn + c;
            float* p1 = Cmat + (size_t)(r + 8) * Nn + c;
            float2 v0 = make_float2(acc[mt][nt][0], acc[mt][nt][1]);
            float2 v1 = make_float2(acc[mt][nt][2], acc[mt][nt][3]);
            if (addTo) {
                float2 o0 = *(float2*)p0, o1 = *(float2*)p1;
                v0.x += o0.x; v0.y += o0.y; v1.x += o1.x; v1.y += o1.y;
            }
            *(float2*)p0 = v0;
            *(float2*)p1 = v1;
        }
    }
}

// ---------------- RoPE tables -------------------------------------------------
__global__ void rope_init_kernel() {
    int idx = blockIdx.x * 256 + threadIdx.x;
    int t = idx >> 5, j = idx & 31;
    float inv = powf(10000.0f, -((float)(2 * j) / (float)DH));
    float ang = (float)t * inv;
    float c = cosf(ang), s = sinf(ang);
    g_cos[t * DH + j]      = c;
    g_cos[t * DH + j + 32] = c;
    g_sin[t * DH + j]      = s;
    g_sin[t * DH + j + 32] = s;
}

// ---------------- input projection: h = x @ w_in^T (K=9) ----------------------
__global__ __launch_bounds__(256) void inproj_kernel(const float* __restrict__ x,
                                                     const float* __restrict__ w,
                                                     float* __restrict__ h) {
    __shared__ float xs[FEAT];
    int m = blockIdx.x;
    if (threadIdx.x < FEAT) xs[threadIdx.x] = x[(size_t)m * FEAT + threadIdx.x];
    __syncthreads();
    for (int c = threadIdx.x; c < C; c += 256) {
        float s = 0.f;
#pragma unroll
        for (int f = 0; f < FEAT; f++) s += xs[f] * w[c * FEAT + f];
        h[(size_t)m * C + c] = s;
    }
}

// ---------------- RMSNorm -----------------------------------------------------
__global__ __launch_bounds__(256) void rms_kernel(const float* __restrict__ in,
                                                  const float* __restrict__ g,
                                                  float* __restrict__ out, int nc) {
    int m = blockIdx.x;
    int tid = threadIdx.x;
    const float* row = in + (size_t)m * nc;
    float ss = 0.f;
    for (int c = tid; c < nc; c += 256) { float v = row[c]; ss += v * v; }
#pragma unroll
    for (int o = 16; o > 0; o >>= 1) ss += __shfl_xor_sync(0xffffffffu, ss, o);
    __shared__ float red[8];
    if ((tid & 31) == 0) red[tid >> 5] = ss;
    __syncthreads();
    if (tid < 8) {
        float v = red[tid];
#pragma unroll
        for (int o = 4; o > 0; o >>= 1) v += __shfl_xor_sync(0xffu, v, o);
        if (tid == 0) red[0] = v;
    }
    __syncthreads();
    float r = rsqrtf(red[0] / (float)nc + 1e-5f);
    for (int c = tid; c < nc; c += 256)
        out[(size_t)m * nc + c] = row[c] * r * g[c];
}

// ---------------- RoPE apply --------------------------------------------------
__global__ __launch_bounds__(256) void rope_kernel(float* __restrict__ buf, int rowStride) {
    int idx = blockIdx.x * 256 + threadIdx.x;
    int j  = idx & 31;
    int hh = (idx >> 5) & (NH - 1);
    int m  = idx >> 9;
    int t  = m & (T - 1);
    float* p = buf + (size_t)m * rowStride + hh * DH;
    float c = g_cos[t * DH + j];
    float s = g_sin[t * DH + j];
    float x0 = p[j], x1 = p[j + 32];
    p[j]      = x0 * c - x1 * s;
    p[j + 32] = x1 * c + x0 * s;
}

// ---------------- flash attention (fp32 SIMT, 1 thread / query) ----------------
__global__ __launch_bounds__(128) void attn_kernel(const float* __restrict__ q,
                                                   const float* __restrict__ kv,
                                                   float* __restrict__ y) {
    __shared__ float Ks[32][DH];
    __shared__ float Vs[32][DH];
    const int tid = threadIdx.x;
    const int b  = blockIdx.y >> 4;
    const int hh = blockIdx.y & 15;
    const int t  = blockIdx.x * 128 + tid;
    const int tEndBlock = blockIdx.x * 128 + 128;

    float qr[DH];
    {
        const float* qp = q + (size_t)(b * T + t) * C + hh * DH;
#pragma unroll
        for (int d = 0; d < DH; d++) qr[d] = qp[d] * 0.125f;
    }
    float orow[DH];
#pragma unroll
    for (int d = 0; d < DH; d++) orow[d] = 0.f;
    float mrun = -1e30f, ssum = 0.f;

    for (int j0 = 0; j0 < tEndBlock; j0 += 32) {
        __syncthreads();
#pragma unroll
        for (int i = 0; i < 4; i++) {
            int lin = tid + i * 128;
            int r   = lin >> 4;
            int c4  = (lin & 15) << 2;
            size_t base = (size_t)(b * T + j0 + r) * (2 * C) + hh * DH + c4;
            *(float4*)&Ks[r][c4] = *(const float4*)(kv + base);
            *(float4*)&Vs[r][c4] = *(const float4*)(kv + base + C);
        }
        __syncthreads();
        int nj = t - j0 + 1;
        if (nj > 32) nj = 32;
        for (int jj = 0; jj < nj; jj++) {
            float s = 0.f;
#pragma unroll
            for (int d = 0; d < DH; d++) s += qr[d] * Ks[jj][d];
            float mnew = fmaxf(mrun, s);
            float corr = __expf(mrun - mnew);
            float p    = __expf(s - mnew);
            ssum = ssum * corr + p;
#pragma unroll
            for (int d = 0; d < DH; d++)
                orow[d] = orow[d] * corr + p * Vs[jj][d];
            mrun = mnew;
        }
    }
    float inv = 1.f / ssum;
    float* yp = y + (size_t)(b * T + t) * C + hh * DH;
#pragma unroll
    for (int d = 0; d < DH; d++) yp[d] = orow[d] * inv;
}

// ---------------- gated SiLU --------------------------------------------------
__global__ void silu_gate_kernel(float* __restrict__ h1, const float* __restrict__ h2, int n) {
    int i = blockIdx.x * blockDim.x + threadIdx.x;
    if (i < n) {
        float a = h1[i];
        float s = a / (1.f + __expf(-a));
        h1[i] = s * h2[i];
    }
}

// ---------------- driver ------------------------------------------------------
extern "C" void kernel_launch(void* const* d_in, const int* in_sizes, int n_in,
                              void* d_out, int out_size) {
    const float* x    = (const float*)d_in[0];
    const float* w_in = (const float*)d_in[1];
    const float* wq   = (const float*)d_in[2];
    const float* wkv  = (const float*)d_in[3];
    const float* wo   = (const float*)d_in[4];
    const float* w1   = (const float*)d_in[5];
    const float* w2   = (const float*)d_in[6];
    const float* w3   = (const float*)d_in[7];
    const float* g1   = (const float*)d_in[8];
    const float* g2   = (const float*)d_in[9];
    const float* gf   = (const float*)d_in[10];

    float *h, *nrm, *qb, *kvb, *yb, *h1, *h2;
    __nv_bfloat16 *a3, *wq3, *wkv3, *wo3, *w13, *w23, *w33;
    cudaGetSymbolAddress((void**)&h,    g_h);
    cudaGetSymbolAddress((void**)&nrm,  g_nrm);
    cudaGetSymbolAddress((void**)&qb,   g_q);
    cudaGetSymbolAddress((void**)&kvb,  g_kv);
    cudaGetSymbolAddress((void**)&yb,   g_y);
    cudaGetSymbolAddress((void**)&h1,   g_h1);
    cudaGetSymbolAddress((void**)&h2,   g_h2);
    cudaGetSymbolAddress((void**)&a3,   g_a3);
    cudaGetSymbolAddress((void**)&wq3,  g_wq3);
    cudaGetSymbolAddress((void**)&wkv3, g_wkv3);
    cudaGetSymbolAddress((void**)&wo3,  g_wo3);
    cudaGetSymbolAddress((void**)&w13,  g_w13);
    cudaGetSymbolAddress((void**)&w23,  g_w23);
    cudaGetSymbolAddress((void**)&w33,  g_w33);

    rope_init_kernel<<<128, 256>>>();
    inproj_kernel<<<M, 256>>>(x, w_in, h);

    // pack all weights (hi/lo bf16 triple)
    {
        int n;
        n = L * C * C;       pack_b3_kernel<<<(n + 255) / 256, 256>>>(wq,  wq3,  C,   n);
        n = L * 2 * C * C;   pack_b3_kernel<<<(n + 255) / 256, 256>>>(wkv, wkv3, C,   n);
        n = L * C * C;       pack_b3_kernel<<<(n + 255) / 256, 256>>>(wo,  wo3,  C,   n);
        n = L * HFF * C;     pack_b3_kernel<<<(n + 255) / 256, 256>>>(w1,  w13,  C,   n);
        n = L * HFF * C;     pack_b3_kernel<<<(n + 255) / 256, 256>>>(w2,  w23,  C,   n);
        n = L * C * HFF;     pack_b3_kernel<<<(n + 255) / 256, 256>>>(w3,  w33,  HFF, n);
    }

    for (int l = 0; l < L; l++) {
        // ---- attention block ----
        rms_kernel<<<M, 256>>>(h, g1 + (size_t)l * C, nrm, C);
        pack_a3_kernel<<<(M * C + 255) / 256, 256>>>(nrm, a3, C, M * C);
        hgemm<<<dim3(C / 128, M / 128), 256>>>(a3, wq3 + (size_t)l * C * KP1, qb, C, KP1, 0);
        hgemm<<<dim3(2 * C / 128, M / 128), 256>>>(a3, wkv3 + (size_t)l * 2 * C * KP1, kvb, 2 * C, KP1, 0);
        rope_kernel<<<4096, 256>>>(qb, C);
        rope_kernel<<<4096, 256>>>(kvb, 2 * C);
        attn_kernel<<<dim3(T / 128, Bsz * NH), 128>>>(qb, kvb, yb);
        pack_a3_kernel<<<(M * C + 255) / 256, 256>>>(yb, a3, C, M * C);
        hgemm<<<dim3(C / 128, M / 128), 256>>>(a3, wo3 + (size_t)l * C * KP1, h, C, KP1, 1);
        // ---- MLP block ----
        rms_kernel<<<M, 256>>>(h, g2 + (size_t)l * C, nrm, C);
        pack_a3_kernel<<<(M * C + 255) / 256, 256>>>(nrm, a3, C, M * C);
        hgemm<<<dim3(HFF / 128, M / 128), 256>>>(a3, w13 + (size_t)l * HFF * KP1, h1, HFF, KP1, 0);
        hgemm<<<dim3(HFF / 128, M / 128), 256>>>(a3, w23 + (size_t)l * HFF * KP1, h2, HFF, KP1, 0);
        silu_gate_kernel<<<(M * HFF + 255) / 256, 256>>>(h1, h2, M * HFF);
        pack_a3_kernel<<<(M * HFF + 255) / 256, 256>>>(h1, a3, HFF, M * HFF);
        hgemm<<<dim3(C / 128, M / 128), 256>>>(a3, w33 + (size_t)l * C * KP3, h, C, KP3, 1);
    }

    rms_kernel<<<M, 256>>>(h, gf, (float*)d_out, C);
}